// round 8
// baseline (speedup 1.0000x reference)
#include <cuda_runtime.h>

// Ragged segment mean, adaptive begin-relative 32-row chunking:
//   seq:   [B=2048, L=512, D=512] fp32   (d_in[0])
//   begin: [B] int32                      (d_in[1])
//   end:   [B] int32                      (d_in[2])
//   out:   [B, D] fp32 = mean(seq[b, begin[b]:end[b], :], axis=0)
//
// cudaMemsetAsync zeroes out. Grid (B, 8); chunk c of batch b covers
// [begin+32c, min(begin+32(c+1), end)) — only ceil(len/32) chunks are
// live (avg ~4.5), the rest exit immediately (proven cheap in R5).
// Live chunks pre-scale by 1/len and merge with one red.global.add.v4.f32
// per thread; single-chunk segments (len<=32) write directly with STG.128.

#define B_DIM    2048
#define L_DIM    512
#define D_DIM    512
#define THREADS  128          // D_DIM / 4 lanes of float4
#define CHUNK    32
#define MAXCHUNK 8            // ceil(256 / 32)

__global__ __launch_bounds__(THREADS)
void ragged_mean_chunk_kernel(const float* __restrict__ seq,
                              const int* __restrict__ begin,
                              const int* __restrict__ end,
                              float* __restrict__ out) {
    const int b = blockIdx.x;
    const int c = blockIdx.y;
    const int t = threadIdx.x;  // owns columns [4t, 4t+4)

    const int sb  = begin[b];
    const int eb  = end[b];
    const int len = eb - sb;    // in [1, 256]

    // Chunk c covers [sb + 32c, min(sb + 32(c+1), eb))
    const int s = sb + CHUNK * c;
    if (s >= eb) return;        // dead chunk for this (short) segment
    int e = s + CHUNK; if (e > eb) e = eb;

    const float4* base =
        reinterpret_cast<const float4*>(seq + (size_t)b * L_DIM * D_DIM) + t;

    float ax = 0.f, ay = 0.f, az = 0.f, aw = 0.f;

    int l = s;
    for (; l + 4 <= e; l += 4) {
        float4 v0 = __ldcs(&base[(size_t)(l + 0) * (D_DIM / 4)]);
        float4 v1 = __ldcs(&base[(size_t)(l + 1) * (D_DIM / 4)]);
        float4 v2 = __ldcs(&base[(size_t)(l + 2) * (D_DIM / 4)]);
        float4 v3 = __ldcs(&base[(size_t)(l + 3) * (D_DIM / 4)]);
        ax += v0.x + v1.x + v2.x + v3.x;
        ay += v0.y + v1.y + v2.y + v3.y;
        az += v0.z + v1.z + v2.z + v3.z;
        aw += v0.w + v1.w + v2.w + v3.w;
    }
    for (; l < e; ++l) {
        float4 v = __ldcs(&base[(size_t)l * (D_DIM / 4)]);
        ax += v.x; ay += v.y; az += v.z; aw += v.w;
    }

    const float inv = 1.0f / (float)len;
    ax *= inv; ay *= inv; az *= inv; aw *= inv;

    float* dst = out + (size_t)b * D_DIM + 4 * t;  // 16B aligned

    if (len <= CHUNK) {
        // Sole writer for this batch row: plain vector store, no atomic.
        *reinterpret_cast<float4*>(dst) = make_float4(ax, ay, az, aw);
    } else {
        // Multiple chunks accumulate: vector reduction, no return.
        asm volatile("red.global.add.v4.f32 [%0], {%1, %2, %3, %4};"
                     :: "l"(dst), "f"(ax), "f"(ay), "f"(az), "f"(aw)
                     : "memory");
    }
}

extern "C" void kernel_launch(void* const* d_in, const int* in_sizes, int n_in,
                              void* d_out, int out_size) {
    const float* seq   = (const float*)d_in[0];
    const int*   begin = (const int*)d_in[1];
    const int*   end   = (const int*)d_in[2];
    float*       out   = (float*)d_out;

    // Zero the accumulation target (async, graph-capturable)
    cudaMemsetAsync(d_out, 0, (size_t)B_DIM * D_DIM * sizeof(float));

    dim3 grid(B_DIM, MAXCHUNK);
    ragged_mean_chunk_kernel<<<grid, THREADS>>>(seq, begin, end, out);
}